// round 13
// baseline (speedup 1.0000x reference)
#include <cuda_runtime.h>
#include <cuda_fp16.h>
#include <cstdint>
#include <cstddef>

#define NROWS 16384

// ---------------- scratch (device globals: no allocations allowed) -------------
// "A-format" (fp16): row-major; within each 64-col k-group, cols permuted:
//   blk=(c>>4)&3, q=c&15, h=q>>3, rem=q&7, t=rem>>1, b=rem&1
//   newc = (c&~63) | (blk<<4) | (t<<2) | (h<<1) | b
// so each mma A-fragment quad (2t,2t+1,2t+8,2t+9) is 8B-contiguous -> LDS.64.
// "B-format" (fp16): per 64-k tile: [16 r][N n][4 halves], r=blk*4+t.
__device__ __align__(16) __half g_H1 [(size_t)NROWS * 512];    // A-format
__device__ __align__(16) __half g_G  [(size_t)NROWS * 2048];   // A-format [F | gamma]
__device__ __align__(16) __half g_AB [(size_t)NROWS * 4096];   // plain row-major fp16
__device__ __align__(16) __half g_H  [(size_t)NROWS * 2048];   // A-format
__device__ __align__(16) __half g_W2p[(size_t)512  * 1024];    // B-format
__device__ __align__(16) __half g_W3p[(size_t)2048 * 4096];    // B-format (fused W3)
__device__ __align__(16) __half g_W4p[(size_t)2048 * 1024];    // B-format
__device__ double g_invden[512];

// ---------------- helpers ----------------

__device__ __forceinline__ int apermc(int c) {  // A-format column permutation
    int blk = (c >> 4) & 3;
    int q   = c & 15;
    int h = q >> 3, rem = q & 7, t = rem >> 1, b = rem & 1;
    return (c & ~63) | (blk << 4) | (t << 2) | (h << 1) | b;
}

__device__ __forceinline__ uint32_t smem_u32(const void* p) {
    uint32_t a;
    asm("{ .reg .u64 t; cvta.to.shared.u64 t, %1; cvt.u32.u64 %0, t; }" : "=r"(a) : "l"(p));
    return a;
}
__device__ __forceinline__ void cp_async16(uint32_t saddr, const void* g) {
    asm volatile("cp.async.cg.shared.global [%0], [%1], 16;" :: "r"(saddr), "l"(g));
}
__device__ __forceinline__ void cp_commit() {
    asm volatile("cp.async.commit_group;" ::: "memory");
}
template<int N> __device__ __forceinline__ void cp_wait() {
    asm volatile("cp.async.wait_group %0;" :: "n"(N) : "memory");
}

// m16n8k16 fp16 -> fp32 acc
__device__ __forceinline__ void mma_f16(float d[4], uint2 ag, uint2 ag8, uint2 b) {
    asm volatile(
        "mma.sync.aligned.m16n8k16.row.col.f32.f16.f16.f32 "
        "{%0,%1,%2,%3}, {%4,%5,%6,%7}, {%8,%9}, {%0,%1,%2,%3};\n"
        : "+f"(d[0]), "+f"(d[1]), "+f"(d[2]), "+f"(d[3])
        : "r"(ag.x), "r"(ag8.x), "r"(ag.y), "r"(ag8.y), "r"(b.x), "r"(b.y));
}

// ---------------- small / packing kernels ----------------

__global__ void invden_kernel() {
    int i = threadIdx.x;
    if (i < 512) {
        double e = -(2.0 * (double)i / 1024.0) * 9.210340371976184; // ln(10000)
        g_invden[i] = exp(e);
    }
}

__global__ void h1_kernel(const float* __restrict__ pos,
                          const float* __restrict__ W1,
                          const float* __restrict__ b1) {
    int k = blockIdx.x;
    int j = threadIdx.x;  // 512
    float p0 = pos[3 * k + 0], p1 = pos[3 * k + 1], p2 = pos[3 * k + 2];
    float v = b1[j];
    v = fmaf(p0, W1[j], v);
    v = fmaf(p1, W1[512 + j], v);
    v = fmaf(p2, W1[1024 + j], v);
    g_H1[(size_t)k * 512 + apermc(j)] = __float2half_rn(fmaxf(v, 0.0f));
}

__global__ void gamma_kernel() {
    int k = blockIdx.x;
    int i = threadIdx.x;  // 512
    double ang = (double)k * g_invden[i];
    const double INV2PI = 0.15915494309189533577;
    const double TWOPI  = 6.2831853071795864769;
    double rr = ang - floor(ang * INV2PI) * TWOPI;
    float s, c;
    sincosf((float)rr, &s, &c);
    int c0 = 1024 + 2 * i;            // even (b=0) -> sin at nc, cos at nc+1
    int nc = apermc(c0);
    *reinterpret_cast<__half2*>(g_G + (size_t)k * 2048 + nc) =
        __floats2half2_rn(s, c);
}

__global__ void combine_kernel(const int* __restrict__ parent,
                               const float* __restrict__ b3) {
    int k = blockIdx.x;
    int t = threadIdx.x;  // 512 threads, 4 cols each
    int p = parent[k];
    int c4 = 4 * t;
    // 4 halves each from AB[k, c4..] and AB[p, 2048+c4..]
    const __half2* a2 = reinterpret_cast<const __half2*>(g_AB + (size_t)k * 4096 + c4);
    const __half2* b2h = reinterpret_cast<const __half2*>(g_AB + (size_t)p * 4096 + 2048 + c4);
    float2 a01 = __half22float2(a2[0]),  a23 = __half22float2(a2[1]);
    float2 p01 = __half22float2(b2h[0]), p23 = __half22float2(b2h[1]);
    const float4 bb = *reinterpret_cast<const float4*>(b3 + c4);
    __half* row = g_H + (size_t)k * 2048;
    int base = apermc(c4);  // cols map to base, base+1, base+4, base+5
    *reinterpret_cast<__half2*>(row + base) =
        __floats2half2_rn(fmaxf(a01.x + p01.x + bb.x, 0.0f),
                          fmaxf(a01.y + p01.y + bb.y, 0.0f));
    *reinterpret_cast<__half2*>(row + base + 4) =
        __floats2half2_rn(fmaxf(a23.x + p23.x + bb.z, 0.0f),
                          fmaxf(a23.y + p23.y + bb.w, 0.0f));
}

// One launch packs W2, fused-W3, W4 into B-format fp16.
__global__ void pack_weights(const float* __restrict__ W2,
                             const float* __restrict__ W3,
                             const float* __restrict__ W4) {
    int bid = blockIdx.x;  // 0..4607
    const float *src0 = nullptr, *src1 = nullptr;
    __half* dstbase;
    int k, N;
    if (bid < 512)       { k = bid;        N = 1024; dstbase = g_W2p; src0 = W2 + (size_t)k * 1024; }
    else if (bid < 2560) { k = bid - 512;  N = 4096; dstbase = g_W3p;
                           src0 = W3 + (size_t)k * 2048;
                           src1 = W3 + (size_t)(2048 + k) * 2048; }
    else                 { k = bid - 2560; N = 1024; dstbase = g_W4p; src0 = W4 + (size_t)k * 1024; }
    int kt = k >> 6, kk = k & 63;
    int blk = kk >> 4, q = kk & 15;
    int h = q >> 3, rem = q & 7, t = rem >> 1, b = rem & 1;
    int r = blk * 4 + t;
    __half* dst = dstbase + ((size_t)(kt * 16 + r) * N) * 4 + h * 2 + b;
    for (int n = threadIdx.x; n < N; n += blockDim.x) {
        float v = (src1 && n >= 2048) ? src1[n - 2048] : src0[n];
        dst[(size_t)n * 4] = __float2half_rn(v);
    }
}

// ---------------- FP16 GEMM (mma.sync m16n8k16, cp.async 4-stage) --------------
// C[M,N] = A(A-format fp16)[M,Kd] * B(B-format fp16)[Kd,N] (+bias).
// CTA tile 128x256, k-tile 64. 512 threads (16 warps 2Mx8N, warp tile 64x32).
// outmode 0: plain fp32 row-major. 1: A-format fp16. 2: plain fp16 row-major.

#define STAGES      4
#define SA_BYTES    (128 * 160)              // 128 rows x (128B data + 32B pad)
#define SB_BYTES    (16 * 2080)              // 16 r-rows x (2048B data + 32B pad)
#define STAGE_BYTES (SA_BYTES + SB_BYTES)    // 53760
#define GEMM_SMEM   (STAGES * STAGE_BYTES)   // 215040

__global__ __launch_bounds__(512, 1)
void gemm_f16(const __half* __restrict__ A, int lda,
              const __half* __restrict__ B, int ldbN,   // full N of B
              float* __restrict__ Cf, int ldc,
              __half* __restrict__ Ch,
              int Kd,
              const float* __restrict__ bias, int outmode) {
    extern __shared__ char smem[];
    const uint32_t uA = smem_u32(smem);
    const uint32_t uB = uA + STAGES * SA_BYTES;

    const int tid  = threadIdx.x;
    const int lane = tid & 31;
    const int wid  = tid >> 5;    // 0..15
    const int g    = lane >> 2;
    const int tig  = lane & 3;
    const int wm   = wid & 1;     // 2 warps in M
    const int wn   = wid >> 1;    // 8 warps in N

    const int blockM = blockIdx.y << 7;
    const int blockN = blockIdx.x << 8;

    float acc[4][4][4];
#pragma unroll
    for (int i = 0; i < 4; i++)
#pragma unroll
        for (int j = 0; j < 4; j++)
#pragma unroll
            for (int c = 0; c < 4; c++)
                acc[i][j][c] = 0.0f;

    // cp.async coords: 2 A-chunks + 4 B-chunks (16B each) per thread per k-tile
    int aRow[2], aOff[2], bR[4], bSeg[4];
#pragma unroll
    for (int i = 0; i < 2; i++) {
        int l = tid + (i << 9);
        aRow[i] = l >> 3;          // 0..127
        aOff[i] = l & 7;           // which 16B of the 128B row
    }
#pragma unroll
    for (int i = 0; i < 4; i++) {
        int l = tid + (i << 9);
        bR[i]   = l >> 7;          // 0..15
        bSeg[i] = l & 127;         // which 16B of the 2048B row
    }

    const int tiles = Kd >> 6;

    auto issue = [&](int kt, int s) {
        const int koff = kt << 6;  // halves
#pragma unroll
        for (int i = 0; i < 2; i++) {
            cp_async16(uA + (uint32_t)(s * SA_BYTES + aRow[i] * 160 + aOff[i] * 16),
                       A + (size_t)(blockM + aRow[i]) * lda + koff + aOff[i] * 8);
        }
#pragma unroll
        for (int i = 0; i < 4; i++) {
            cp_async16(uB + (uint32_t)(s * SB_BYTES + bR[i] * 2080 + bSeg[i] * 16),
                       B + ((size_t)(kt * 16 + bR[i]) * ldbN + blockN + bSeg[i] * 2) * 4);
        }
    };

    // prologue: 3 tiles in flight
    issue(0, 0); cp_commit();
    issue(1, 1); cp_commit();
    issue(2, 2); cp_commit();

    for (int kt = 0; kt < tiles; kt++) {
        cp_wait<2>();
        __syncthreads();
        {   // refill the buffer freed in iteration kt-1
            int nk = kt + 3;
            if (nk < tiles) issue(nk, nk % STAGES);
            cp_commit();
        }

        const int buf = kt % STAGES;
        const uint2* cA = reinterpret_cast<const uint2*>(smem + buf * SA_BYTES);
        const uint2* cB = reinterpret_cast<const uint2*>(smem + STAGES * SA_BYTES + buf * SB_BYTES);

#pragma unroll
        for (int ks = 0; ks < 4; ks++) {
            uint2 ag[4], ag8[4], bf[4];
#pragma unroll
            for (int mt = 0; mt < 4; mt++) {
                int m0 = (wm << 6) + (mt << 4) + g;
                int idx = m0 * 20 + (ks << 2) + tig;       // row stride = 160B = 20 uint2
                ag[mt]  = cA[idx];
                ag8[mt] = cA[idx + 8 * 20];
            }
#pragma unroll
            for (int nt = 0; nt < 4; nt++) {
                int n0 = (wn << 5) + (nt << 3) + g;
                bf[nt] = cB[((ks << 2) + tig) * 260 + n0]; // r stride = 2080B = 260 uint2
            }
#pragma unroll
            for (int mt = 0; mt < 4; mt++)
#pragma unroll
                for (int nt = 0; nt < 4; nt++)
                    mma_f16(acc[mt][nt], ag[mt], ag8[mt], bf[nt]);
        }
    }

    // ---------------- epilogue ----------------
#pragma unroll
    for (int mt = 0; mt < 4; mt++) {
#pragma unroll
        for (int nt = 0; nt < 4; nt++) {
            int row = blockM + (wm << 6) + (mt << 4) + g;
            int col = blockN + (wn << 5) + (nt << 3) + (tig << 1);
            float bv0 = 0.0f, bv1 = 0.0f;
            if (bias) { bv0 = bias[col]; bv1 = bias[col + 1]; }
            float o0 = acc[mt][nt][0] + bv0;
            float o1 = acc[mt][nt][1] + bv1;
            float o2 = acc[mt][nt][2] + bv0;
            float o3 = acc[mt][nt][3] + bv1;
            if (outmode == 0) {
                float2 v0; v0.x = o0; v0.y = o1;
                float2 v1; v1.x = o2; v1.y = o3;
                *reinterpret_cast<float2*>(Cf + (size_t)row * ldc + col)       = v0;
                *reinterpret_cast<float2*>(Cf + (size_t)(row + 8) * ldc + col) = v1;
            } else if (outmode == 1) {
                int nc = apermc(col);  // col even -> (nc, nc+1) contiguous
                *reinterpret_cast<__half2*>(Ch + (size_t)row * ldc + nc)       = __floats2half2_rn(o0, o1);
                *reinterpret_cast<__half2*>(Ch + (size_t)(row + 8) * ldc + nc) = __floats2half2_rn(o2, o3);
            } else {
                *reinterpret_cast<__half2*>(Ch + (size_t)row * ldc + col)       = __floats2half2_rn(o0, o1);
                *reinterpret_cast<__half2*>(Ch + (size_t)(row + 8) * ldc + col) = __floats2half2_rn(o2, o3);
            }
        }
    }
}

// ---------------- launch ----------------

extern "C" void kernel_launch(void* const* d_in, const int* in_sizes, int n_in,
                              void* d_out, int out_size) {
    const float* pos    = (const float*)d_in[0];
    const int*   parent = (const int*)d_in[1];
    const float* W1 = (const float*)d_in[2];
    const float* b1 = (const float*)d_in[3];
    const float* W2 = (const float*)d_in[4];
    const float* b2 = (const float*)d_in[5];
    const float* W3 = (const float*)d_in[6];
    const float* b3 = (const float*)d_in[7];
    const float* W4 = (const float*)d_in[8];
    const float* b4 = (const float*)d_in[9];
    float* out = (float*)d_out;

    __half *pH1, *pG, *pABh, *pH, *pW2p, *pW3p, *pW4p;
    cudaGetSymbolAddress((void**)&pH1,  g_H1);
    cudaGetSymbolAddress((void**)&pG,   g_G);
    cudaGetSymbolAddress((void**)&pABh, g_AB);
    cudaGetSymbolAddress((void**)&pH,   g_H);
    cudaGetSymbolAddress((void**)&pW2p, g_W2p);
    cudaGetSymbolAddress((void**)&pW3p, g_W3p);
    cudaGetSymbolAddress((void**)&pW4p, g_W4p);
    cudaFuncSetAttribute(gemm_f16, cudaFuncAttributeMaxDynamicSharedMemorySize, GEMM_SMEM);

    // 0..3: front-end
    invden_kernel<<<1, 512>>>();
    h1_kernel<<<NROWS, 512>>>(pos, W1, b1);
    gamma_kernel<<<NROWS, 512>>>();
    pack_weights<<<4608, 256>>>(W2, W3, W4);

    // 4: GEMM1: F = H1 @ W2 + b2 -> g_G[:, perm 0:1024] (A-format fp16 out)
    gemm_f16<<<dim3(4, 128), 512, GEMM_SMEM>>>(pH1, 512, pW2p, 1024,
                                               nullptr, 2048, pG, 512, b2, 1);
    // 5: GEMM2: AB = G @ [W3top|W3bot]  [16384,2048]x[2048,4096] -> fp16 plain
    gemm_f16<<<dim3(16, 128), 512, GEMM_SMEM>>>(pG, 2048, pW3p, 4096,
                                                nullptr, 4096, pABh, 2048, nullptr, 2);
    // 6: combine -> g_H (A-format fp16)
    combine_kernel<<<NROWS, 512>>>(parent, b3);
    // 7: GEMM3: out = H @ W4 + b4 -> fp32 plain
    gemm_f16<<<dim3(4, 128), 512, GEMM_SMEM>>>(pH, 2048, pW4p, 1024,
                                               out, 1024, nullptr, 2048, b4, 0);
}

// round 15
// speedup vs baseline: 1.0747x; 1.0747x over previous
#include <cuda_runtime.h>
#include <cuda_fp16.h>
#include <cstdint>
#include <cstddef>

#define NROWS 16384

// ---------------- scratch (device globals: no allocations allowed) -------------
// "A-format" (fp16): row-major; within each 64-col k-group, cols permuted:
//   blk=(c>>4)&3, q=c&15, h=q>>3, rem=q&7, t=rem>>1, b=rem&1
//   newc = (c&~63) | (blk<<4) | (t<<2) | (h<<1) | b
// so each mma A-fragment quad (2t,2t+1,2t+8,2t+9) is 8B-contiguous -> LDS.64.
// "B-format" (fp16): per 64-k tile: [16 r][N n][4 halves], r=blk*4+t.
__device__ __align__(16) __half g_H1 [(size_t)NROWS * 512];    // A-format
__device__ __align__(16) __half g_G  [(size_t)NROWS * 2048];   // A-format [F | gamma]
__device__ __align__(16) __half g_AB [(size_t)NROWS * 4096];   // plain row-major fp16
__device__ __align__(16) __half g_H  [(size_t)NROWS * 2048];   // A-format
__device__ __align__(16) __half g_W2p[(size_t)512  * 1024];    // B-format
__device__ __align__(16) __half g_W3p[(size_t)2048 * 4096];    // B-format (fused W3)
__device__ __align__(16) __half g_W4p[(size_t)2048 * 1024];    // B-format
__device__ double g_invden[512];

// ---------------- helpers ----------------

__device__ __forceinline__ int apermc(int c) {  // A-format column permutation
    int blk = (c >> 4) & 3;
    int q   = c & 15;
    int h = q >> 3, rem = q & 7, t = rem >> 1, b = rem & 1;
    return (c & ~63) | (blk << 4) | (t << 2) | (h << 1) | b;
}

__device__ __forceinline__ uint32_t smem_u32(const void* p) {
    uint32_t a;
    asm("{ .reg .u64 t; cvta.to.shared.u64 t, %1; cvt.u32.u64 %0, t; }" : "=r"(a) : "l"(p));
    return a;
}
__device__ __forceinline__ void cp_async16(uint32_t saddr, const void* g) {
    asm volatile("cp.async.cg.shared.global [%0], [%1], 16;" :: "r"(saddr), "l"(g));
}
__device__ __forceinline__ void cp_commit() {
    asm volatile("cp.async.commit_group;" ::: "memory");
}
template<int N> __device__ __forceinline__ void cp_wait() {
    asm volatile("cp.async.wait_group %0;" :: "n"(N) : "memory");
}

// m16n8k16 fp16 -> fp32 acc
__device__ __forceinline__ void mma_f16(float d[4], uint2 ag, uint2 ag8, uint2 b) {
    asm volatile(
        "mma.sync.aligned.m16n8k16.row.col.f32.f16.f16.f32 "
        "{%0,%1,%2,%3}, {%4,%5,%6,%7}, {%8,%9}, {%0,%1,%2,%3};\n"
        : "+f"(d[0]), "+f"(d[1]), "+f"(d[2]), "+f"(d[3])
        : "r"(ag.x), "r"(ag8.x), "r"(ag.y), "r"(ag8.y), "r"(b.x), "r"(b.y));
}

// ---------------- small / packing kernels ----------------

__global__ void invden_kernel() {
    int i = threadIdx.x;
    if (i < 512) {
        double e = -(2.0 * (double)i / 1024.0) * 9.210340371976184; // ln(10000)
        g_invden[i] = exp(e);
    }
}

__global__ void h1_kernel(const float* __restrict__ pos,
                          const float* __restrict__ W1,
                          const float* __restrict__ b1) {
    int k = blockIdx.x;
    int j = threadIdx.x;  // 512
    float p0 = pos[3 * k + 0], p1 = pos[3 * k + 1], p2 = pos[3 * k + 2];
    float v = b1[j];
    v = fmaf(p0, W1[j], v);
    v = fmaf(p1, W1[512 + j], v);
    v = fmaf(p2, W1[1024 + j], v);
    g_H1[(size_t)k * 512 + apermc(j)] = __float2half_rn(fmaxf(v, 0.0f));
}

__global__ void gamma_kernel() {
    int k = blockIdx.x;
    int i = threadIdx.x;  // 512
    double ang = (double)k * g_invden[i];
    const double INV2PI = 0.15915494309189533577;
    const double TWOPI  = 6.2831853071795864769;
    double rr = ang - floor(ang * INV2PI) * TWOPI;
    float s, c;
    sincosf((float)rr, &s, &c);
    int c0 = 1024 + 2 * i;            // even (b=0) -> sin at nc, cos at nc+1
    int nc = apermc(c0);
    *reinterpret_cast<__half2*>(g_G + (size_t)k * 2048 + nc) =
        __floats2half2_rn(s, c);
}

__global__ void combine_kernel(const int* __restrict__ parent,
                               const float* __restrict__ b3) {
    int k = blockIdx.x;
    int t = threadIdx.x;  // 512 threads, 4 cols each
    int p = parent[k];
    int c4 = 4 * t;
    const __half2* a2  = reinterpret_cast<const __half2*>(g_AB + (size_t)k * 4096 + c4);
    const __half2* b2h = reinterpret_cast<const __half2*>(g_AB + (size_t)p * 4096 + 2048 + c4);
    float2 a01 = __half22float2(a2[0]),  a23 = __half22float2(a2[1]);
    float2 p01 = __half22float2(b2h[0]), p23 = __half22float2(b2h[1]);
    const float4 bb = *reinterpret_cast<const float4*>(b3 + c4);
    __half* row = g_H + (size_t)k * 2048;
    int base = apermc(c4);  // cols map to base, base+1, base+4, base+5
    *reinterpret_cast<__half2*>(row + base) =
        __floats2half2_rn(fmaxf(a01.x + p01.x + bb.x, 0.0f),
                          fmaxf(a01.y + p01.y + bb.y, 0.0f));
    *reinterpret_cast<__half2*>(row + base + 4) =
        __floats2half2_rn(fmaxf(a23.x + p23.x + bb.z, 0.0f),
                          fmaxf(a23.y + p23.y + bb.w, 0.0f));
}

// One launch packs W2, fused-W3, W4 into B-format fp16.
__global__ void pack_weights(const float* __restrict__ W2,
                             const float* __restrict__ W3,
                             const float* __restrict__ W4) {
    int bid = blockIdx.x;  // 0..4607
    const float *src0 = nullptr, *src1 = nullptr;
    __half* dstbase;
    int k, N;
    if (bid < 512)       { k = bid;        N = 1024; dstbase = g_W2p; src0 = W2 + (size_t)k * 1024; }
    else if (bid < 2560) { k = bid - 512;  N = 4096; dstbase = g_W3p;
                           src0 = W3 + (size_t)k * 2048;
                           src1 = W3 + (size_t)(2048 + k) * 2048; }
    else                 { k = bid - 2560; N = 1024; dstbase = g_W4p; src0 = W4 + (size_t)k * 1024; }
    int kt = k >> 6, kk = k & 63;
    int blk = kk >> 4, q = kk & 15;
    int h = q >> 3, rem = q & 7, t = rem >> 1, b = rem & 1;
    int r = blk * 4 + t;
    __half* dst = dstbase + ((size_t)(kt * 16 + r) * N) * 4 + h * 2 + b;
    for (int n = threadIdx.x; n < N; n += blockDim.x) {
        float v = (src1 && n >= 2048) ? src1[n - 2048] : src0[n];
        dst[(size_t)n * 4] = __float2half_rn(v);
    }
}

// ---------------- FP16 GEMM (mma.sync m16n8k16, cp.async 3-stage) --------------
// C[M,N] = A(A-format fp16)[M,Kd] * B(B-format fp16)[Kd,N] (+bias).
// CTA tile 128x128, k-tile 64. 256 threads (8 warps 2Mx4N, warp tile 64x32).
// 2 CTAs/SM.  outmode 0: fp32 row-major. 1: A-format fp16. 2: fp16 row-major.

#define STAGES      3
#define SA_BYTES    (128 * 160)              // 128 rows x (128B data + 32B pad)
#define SB_BYTES    (16 * 1056)              // 16 r-rows x (1024B data + 32B pad)
#define STAGE_BYTES (SA_BYTES + SB_BYTES)    // 37376
#define GEMM_SMEM   (STAGES * STAGE_BYTES)   // 112128

__global__ __launch_bounds__(256, 2)
void gemm_f16(const __half* __restrict__ A, int lda,
              const __half* __restrict__ B, int ldbN,   // full N of B
              float* __restrict__ Cf, int ldc,
              __half* __restrict__ Ch,
              int Kd,
              const float* __restrict__ bias, int outmode) {
    extern __shared__ char smem[];
    const uint32_t uA = smem_u32(smem);
    const uint32_t uB = uA + STAGES * SA_BYTES;

    const int tid  = threadIdx.x;
    const int lane = tid & 31;
    const int wid  = tid >> 5;
    const int g    = lane >> 2;
    const int tig  = lane & 3;
    const int wm   = wid & 1;     // 2 warps in M
    const int wn   = wid >> 1;    // 4 warps in N

    const int blockM = blockIdx.y << 7;
    const int blockN = blockIdx.x << 7;

    float acc[4][4][4];
#pragma unroll
    for (int i = 0; i < 4; i++)
#pragma unroll
        for (int j = 0; j < 4; j++)
#pragma unroll
            for (int c = 0; c < 4; c++)
                acc[i][j][c] = 0.0f;

    // cp.async coords: 4 A-chunks + 4 B-chunks (16B each) per thread per k-tile
    int aRow[4], aOff[4], bR[4], bSeg[4];
#pragma unroll
    for (int i = 0; i < 4; i++) {
        int l = tid + (i << 8);
        aRow[i] = l >> 3;          // 0..127
        aOff[i] = l & 7;           // which 16B of the 128B row
        bR[i]   = l >> 6;          // 0..15
        bSeg[i] = l & 63;          // which 16B of the 1024B row
    }

    const int tiles = Kd >> 6;

    auto issue = [&](int kt, int s) {
        const int koff = kt << 6;  // halves
#pragma unroll
        for (int i = 0; i < 4; i++) {
            cp_async16(uA + (uint32_t)(s * SA_BYTES + aRow[i] * 160 + aOff[i] * 16),
                       A + (size_t)(blockM + aRow[i]) * lda + koff + aOff[i] * 8);
            cp_async16(uB + (uint32_t)(s * SB_BYTES + bR[i] * 1056 + bSeg[i] * 16),
                       B + ((size_t)(kt * 16 + bR[i]) * ldbN + blockN + bSeg[i] * 2) * 4);
        }
    };

    // prologue: 2 tiles in flight
    issue(0, 0); cp_commit();
    issue(1, 1); cp_commit();

    for (int kt = 0; kt < tiles; kt++) {
        cp_wait<1>();
        __syncthreads();
        {   // refill the buffer freed in iteration kt-1
            int nk = kt + 2;
            if (nk < tiles) issue(nk, nk % STAGES);
            cp_commit();
        }

        const int buf = kt % STAGES;
        const uint2* cA = reinterpret_cast<const uint2*>(smem + buf * SA_BYTES);
        const uint2* cB = reinterpret_cast<const uint2*>(smem + STAGES * SA_BYTES + buf * SB_BYTES);

#pragma unroll
        for (int ks = 0; ks < 4; ks++) {
            uint2 ag[4], ag8[4], bf[4];
#pragma unroll
            for (int mt = 0; mt < 4; mt++) {
                int m0 = (wm << 6) + (mt << 4) + g;
                int idx = m0 * 20 + (ks << 2) + tig;       // row stride = 160B = 20 uint2
                ag[mt]  = cA[idx];
                ag8[mt] = cA[idx + 8 * 20];
            }
#pragma unroll
            for (int nt = 0; nt < 4; nt++) {
                int n0 = (wn << 5) + (nt << 3) + g;
                bf[nt] = cB[((ks << 2) + tig) * 132 + n0]; // r stride = 1056B = 132 uint2
            }
#pragma unroll
            for (int mt = 0; mt < 4; mt++)
#pragma unroll
                for (int nt = 0; nt < 4; nt++)
                    mma_f16(acc[mt][nt], ag[mt], ag8[mt], bf[nt]);
        }
    }

    // ---------------- epilogue ----------------
#pragma unroll
    for (int mt = 0; mt < 4; mt++) {
#pragma unroll
        for (int nt = 0; nt < 4; nt++) {
            int row = blockM + (wm << 6) + (mt << 4) + g;
            int col = blockN + (wn << 5) + (nt << 3) + (tig << 1);
            float bv0 = 0.0f, bv1 = 0.0f;
            if (bias) { bv0 = bias[col]; bv1 = bias[col + 1]; }
            float o0 = acc[mt][nt][0] + bv0;
            float o1 = acc[mt][nt][1] + bv1;
            float o2 = acc[mt][nt][2] + bv0;
            float o3 = acc[mt][nt][3] + bv1;
            if (outmode == 0) {
                float2 v0; v0.x = o0; v0.y = o1;
                float2 v1; v1.x = o2; v1.y = o3;
                *reinterpret_cast<float2*>(Cf + (size_t)row * ldc + col)       = v0;
                *reinterpret_cast<float2*>(Cf + (size_t)(row + 8) * ldc + col) = v1;
            } else if (outmode == 1) {
                int nc = apermc(col);  // col even -> (nc, nc+1) contiguous
                *reinterpret_cast<__half2*>(Ch + (size_t)row * ldc + nc)       = __floats2half2_rn(o0, o1);
                *reinterpret_cast<__half2*>(Ch + (size_t)(row + 8) * ldc + nc) = __floats2half2_rn(o2, o3);
            } else {
                *reinterpret_cast<__half2*>(Ch + (size_t)row * ldc + col)       = __floats2half2_rn(o0, o1);
                *reinterpret_cast<__half2*>(Ch + (size_t)(row + 8) * ldc + col) = __floats2half2_rn(o2, o3);
            }
        }
    }
}

// ---------------- launch ----------------

extern "C" void kernel_launch(void* const* d_in, const int* in_sizes, int n_in,
                              void* d_out, int out_size) {
    const float* pos    = (const float*)d_in[0];
    const int*   parent = (const int*)d_in[1];
    const float* W1 = (const float*)d_in[2];
    const float* b1 = (const float*)d_in[3];
    const float* W2 = (const float*)d_in[4];
    const float* b2 = (const float*)d_in[5];
    const float* W3 = (const float*)d_in[6];
    const float* b3 = (const float*)d_in[7];
    const float* W4 = (const float*)d_in[8];
    const float* b4 = (const float*)d_in[9];
    float* out = (float*)d_out;

    __half *pH1, *pG, *pABh, *pH, *pW2p, *pW3p, *pW4p;
    cudaGetSymbolAddress((void**)&pH1,  g_H1);
    cudaGetSymbolAddress((void**)&pG,   g_G);
    cudaGetSymbolAddress((void**)&pABh, g_AB);
    cudaGetSymbolAddress((void**)&pH,   g_H);
    cudaGetSymbolAddress((void**)&pW2p, g_W2p);
    cudaGetSymbolAddress((void**)&pW3p, g_W3p);
    cudaGetSymbolAddress((void**)&pW4p, g_W4p);
    cudaFuncSetAttribute(gemm_f16, cudaFuncAttributeMaxDynamicSharedMemorySize, GEMM_SMEM);

    // 0..3: front-end
    invden_kernel<<<1, 512>>>();
    h1_kernel<<<NROWS, 512>>>(pos, W1, b1);
    gamma_kernel<<<NROWS, 512>>>();
    pack_weights<<<4608, 256>>>(W2, W3, W4);

    // 4: GEMM1: F = H1 @ W2 + b2 -> g_G[:, perm 0:1024] (A-format fp16 out)
    gemm_f16<<<dim3(8, 128), 256, GEMM_SMEM>>>(pH1, 512, pW2p, 1024,
                                               nullptr, 2048, pG, 512, b2, 1);
    // 5: GEMM2: AB = G @ [W3top|W3bot]  [16384,2048]x[2048,4096] -> fp16 plain
    gemm_f16<<<dim3(32, 128), 256, GEMM_SMEM>>>(pG, 2048, pW3p, 4096,
                                                nullptr, 4096, pABh, 2048, nullptr, 2);
    // 6: combine -> g_H (A-format fp16)
    combine_kernel<<<NROWS, 512>>>(parent, b3);
    // 7: GEMM3: out = H @ W4 + b4 -> fp32 plain
    gemm_f16<<<dim3(8, 128), 256, GEMM_SMEM>>>(pH, 2048, pW4p, 1024,
                                               out, 1024, nullptr, 2048, b4, 0);
}